// round 3
// baseline (speedup 1.0000x reference)
#include <cuda_runtime.h>
#include <cstdint>

#define BN 512     // batch (i and j)
#define HH 512     // hidden
#define DX 128     // dim_x = dim_y

// Scratch (device globals: no allocation allowed in kernel_launch)
__device__ __align__(16) float hxT_g[HH * BN];      // [h][i]  = x@W1x + b1
__device__ __align__(16) float nhyT_g[HH * BN];     // [h][j]  = -(y@W1y)
__device__ __align__(16) float part_g[8 * BN * BN]; // per-h-chunk partials

// Packed fp32x2 helpers (Blackwell)
#define PACK2(out, lo, hi) \
    asm("mov.b64 %0, {%1, %2};" : "=l"(out) : "f"(lo), "f"(hi))
#define UNPACK2(lo, hi, in) \
    asm("mov.b64 {%0, %1}, %2;" : "=f"(lo), "=f"(hi) : "l"(in))
#define FMA2(acc, a, b) \
    asm("fma.rn.f32x2 %0, %1, %2, %0;" : "+l"(acc) : "l"(a), "l"(b))

// ---------------------------------------------------------------------------
// prep: fused GEMM over stacked rows R = [x; y] (1024 rows, K=128).
//   rows 0..511   -> hxT_g[h][r]  =  x@W1[0:128]  + b1
//   rows 512..1023-> nhyT_g[h][r] = -(y@W1[128:256])
// grid (16 r-tiles, 8 h-tiles), 256 threads, tile 64r x 64h, thread 4r x 4h.
// K staged in 2 chunks of 64. FMA2 inner loop with next-k fragment prefetch.
// ---------------------------------------------------------------------------
__global__ void __launch_bounds__(256) prep_kernel(
    const float* __restrict__ x, const float* __restrict__ y,
    const float* __restrict__ W1, const float* __restrict__ b1)
{
    __shared__ float As[64][64];   // [k][r]
    __shared__ float Ws[64][64];   // [k][h]

    const bool isY = (blockIdx.x >= 8);
    const int r0   = (isY ? (blockIdx.x - 8) : blockIdx.x) * 64;
    const int h0   = blockIdx.y * 64;
    const float* __restrict__ in = isY ? y : x;
    const int wrow0 = isY ? DX : 0;

    const int tid = threadIdx.x;
    const int tr  = tid & 15;    // r frag = tr*4
    const int th  = tid >> 4;    // 0..15 : h frag = th*4

    uint64_t acc[4][2] = {};     // [h][r-pair], packed fp32x2

    const int sr = tid & 63;         // staging: row
    const int sg = tid >> 6;         // staging: k-group (0..3)

    for (int kc = 0; kc < 2; kc++) {
        __syncthreads();
        // stage input tile transposed: As[k][r]
        #pragma unroll
        for (int m = 0; m < 4; m++) {
            int k0 = sg * 16 + m * 4;
            float4 v = *(const float4*)(in + (r0 + sr) * DX + kc * 64 + k0);
            As[k0 + 0][sr] = v.x;
            As[k0 + 1][sr] = v.y;
            As[k0 + 2][sr] = v.z;
            As[k0 + 3][sr] = v.w;
        }
        // stage W1 tile [64k x 64h]
        #pragma unroll
        for (int m = 0; m < 4; m++) {
            int f = tid + 256 * m;          // float4 index 0..1023
            int k = f >> 4, q = f & 15;
            *(float4*)&Ws[k][q * 4] =
                *(const float4*)(W1 + (wrow0 + kc * 64 + k) * HH + h0 + q * 4);
        }
        __syncthreads();

        // fragment double-buffer over k
        float4 av = *(const float4*)&As[0][tr * 4];
        float4 wv = *(const float4*)&Ws[0][th * 4];
        #pragma unroll
        for (int k = 0; k < 64; k++) {
            float4 an, wn;
            if (k < 63) {
                an = *(const float4*)&As[k + 1][tr * 4];
                wn = *(const float4*)&Ws[k + 1][th * 4];
            }
            uint64_t a01, a23, wd;
            PACK2(a01, av.x, av.y);
            PACK2(a23, av.z, av.w);
            PACK2(wd, wv.x, wv.x);
            FMA2(acc[0][0], a01, wd);
            FMA2(acc[0][1], a23, wd);
            PACK2(wd, wv.y, wv.y);
            FMA2(acc[1][0], a01, wd);
            FMA2(acc[1][1], a23, wd);
            PACK2(wd, wv.z, wv.z);
            FMA2(acc[2][0], a01, wd);
            FMA2(acc[2][1], a23, wd);
            PACK2(wd, wv.w, wv.w);
            FMA2(acc[3][0], a01, wd);
            FMA2(acc[3][1], a23, wd);
            av = an; wv = wn;
        }
    }

    float* outg = isY ? nhyT_g : hxT_g;
    #pragma unroll
    for (int c = 0; c < 4; c++) {
        const int h = h0 + th * 4 + c;
        float v0, v1, v2, v3;
        UNPACK2(v0, v1, acc[c][0]);
        UNPACK2(v2, v3, acc[c][1]);
        float4 o;
        if (isY) { o.x = -v0; o.y = -v1; o.z = -v2; o.w = -v3; }
        else {
            float bb = b1[h];
            o.x = v0 + bb; o.y = v1 + bb; o.z = v2 + bb; o.w = v3 + bb;
        }
        *(float4*)(outg + h * BN + r0 + tr * 4) = o;
    }
}

// ---------------------------------------------------------------------------
// main: partial[z][i,j] = sum_{h in chunk z} max(hx[i,h], -hy[j,h])*w2[h]
//                         + sum_{h in chunk z} hy[j,h]*w2[h]        (gy part)
// grid (4 j-tiles, 4 i-tiles, 8 h-chunks) = 128 blocks, 512 threads.
// block tile 128i x 128j x 64h; thread tile 4i x 8j (j split {lo,hi+64}).
// ---------------------------------------------------------------------------
__global__ void __launch_bounds__(512) main_kernel(const float* __restrict__ W2)
{
    __shared__ float Axs[32][128];   // [h][i]
    __shared__ float Bys[32][128];   // [h][j] (negated hy)
    __shared__ float w2s[32];
    __shared__ float gybuf[4][128];

    const int j0 = blockIdx.x * 128;
    const int i0 = blockIdx.y * 128;
    const int hb = blockIdx.z * 64;

    const int tid = threadIdx.x;
    const int ti  = tid >> 4;    // 0..31 : i frag = ti*4
    const int tj  = tid & 15;    // j frags = tj*4 and 64 + tj*4
    const int gq  = tid >> 7;    // 0..3 gy strip
    const int gj  = tid & 127;   // gy j index

    float acc[4][8] = {};
    float gyp = 0.f;

    for (int s = 0; s < 2; s++) {
        const int h0 = hb + s * 32;
        __syncthreads();
        for (int t = tid; t < 1024; t += 512) {
            int h = t >> 5, q = t & 31;
            *(float4*)&Axs[h][q * 4] =
                *(const float4*)(hxT_g + (h0 + h) * BN + i0 + q * 4);
        }
        for (int t = tid; t < 1024; t += 512) {
            int h = t >> 5, q = t & 31;
            *(float4*)&Bys[h][q * 4] =
                *(const float4*)(nhyT_g + (h0 + h) * BN + j0 + q * 4);
        }
        if (tid < 32) w2s[tid] = W2[h0 + tid];
        __syncthreads();

        // fragment double-buffer over h
        float4 a  = *(const float4*)&Axs[0][ti * 4];
        float4 b0 = *(const float4*)&Bys[0][tj * 4];
        float4 b1v= *(const float4*)&Bys[0][64 + tj * 4];
        #pragma unroll
        for (int h = 0; h < 32; h++) {
            float4 an, bn0, bn1;
            if (h < 31) {
                an  = *(const float4*)&Axs[h + 1][ti * 4];
                bn0 = *(const float4*)&Bys[h + 1][tj * 4];
                bn1 = *(const float4*)&Bys[h + 1][64 + tj * 4];
            }
            const float w = w2s[h];
            float av[4] = {a.x, a.y, a.z, a.w};
            float bv[8] = {b0.x, b0.y, b0.z, b0.w, b1v.x, b1v.y, b1v.z, b1v.w};
            #pragma unroll
            for (int r = 0; r < 4; r++)
                #pragma unroll
                for (int c = 0; c < 8; c++)
                    acc[r][c] = fmaf(fmaxf(av[r], bv[c]), w, acc[r][c]);
            a = an; b0 = bn0; b1v = bn1;
        }

        // gy partial: strip gq covers h = gq*8 .. gq*8+7 of this 32-h stage
        #pragma unroll
        for (int hh = 0; hh < 8; hh++) {
            int h = gq * 8 + hh;
            gyp = fmaf(Bys[h][gj], w2s[h], gyp);   // accumulates -(hy*w2)
        }
    }

    __syncthreads();
    gybuf[gq][gj] = gyp;
    __syncthreads();

    float gyv[8];
    #pragma unroll
    for (int c = 0; c < 8; c++) {
        int jl = (c < 4) ? (tj * 4 + c) : (64 + tj * 4 + (c - 4));
        gyv[c] = -(gybuf[0][jl] + gybuf[1][jl] + gybuf[2][jl] + gybuf[3][jl]);
    }

    float* p = part_g + blockIdx.z * (BN * BN);
    #pragma unroll
    for (int r = 0; r < 4; r++) {
        float4 o0, o1;
        o0.x = acc[r][0] + gyv[0];
        o0.y = acc[r][1] + gyv[1];
        o0.z = acc[r][2] + gyv[2];
        o0.w = acc[r][3] + gyv[3];
        o1.x = acc[r][4] + gyv[4];
        o1.y = acc[r][5] + gyv[5];
        o1.z = acc[r][6] + gyv[6];
        o1.w = acc[r][7] + gyv[7];
        const int row = i0 + ti * 4 + r;
        *(float4*)(p + row * BN + j0 + tj * 4) = o0;
        *(float4*)(p + row * BN + j0 + 64 + tj * 4) = o1;
    }
}

// ---------------------------------------------------------------------------
// reduce: out = sum of 8 partials + b2
// ---------------------------------------------------------------------------
__global__ void __launch_bounds__(256) reduce_kernel(
    const float* __restrict__ b2, float* __restrict__ out)
{
    int idx = blockIdx.x * 256 + threadIdx.x;     // float4 index, 65536 total
    const float4* p = (const float4*)part_g;
    float4 s = p[idx];
    #pragma unroll
    for (int k = 1; k < 8; k++) {
        float4 v = p[idx + k * 65536];
        s.x += v.x; s.y += v.y; s.z += v.z; s.w += v.w;
    }
    float bb = b2[0];
    s.x += bb; s.y += bb; s.z += bb; s.w += bb;
    ((float4*)out)[idx] = s;
}

// ---------------------------------------------------------------------------
extern "C" void kernel_launch(void* const* d_in, const int* in_sizes, int n_in,
                              void* d_out, int out_size)
{
    const float* x  = (const float*)d_in[0];
    const float* y  = (const float*)d_in[1];
    const float* W1 = (const float*)d_in[2];
    const float* b1 = (const float*)d_in[3];
    const float* W2 = (const float*)d_in[4];
    const float* b2 = (const float*)d_in[5];
    float* out = (float*)d_out;

    prep_kernel<<<dim3(16, 8), 256>>>(x, y, W1, b1);
    main_kernel<<<dim3(4, 4, 8), 512>>>(W2);
    reduce_kernel<<<256, 256>>>(b2, out);
}

// round 5
// speedup vs baseline: 1.1430x; 1.1430x over previous
#include <cuda_runtime.h>
#include <cstdint>

#define BN 512     // batch (i and j)
#define HH 512     // hidden
#define DX 128     // dim_x = dim_y

// Scratch (device globals). K is split into two halves; main adds them.
__device__ __align__(16) float hxT_g[2 * HH * BN];   // [kc][h][i]
__device__ __align__(16) float nhyT_g[2 * HH * BN];  // [kc][h][j] (negated)
__device__ __align__(16) float part_g[8 * BN * BN];  // per-h-chunk partials

// Packed fp32x2 helpers (Blackwell)
#define PACK2(out, lo, hi) \
    asm("mov.b64 %0, {%1, %2};" : "=l"(out) : "f"(lo), "f"(hi))
#define UNPACK2(lo, hi, in) \
    asm("mov.b64 {%0, %1}, %2;" : "=f"(lo), "=f"(hi) : "l"(in))
#define FMA2(acc, a, b) \
    asm("fma.rn.f32x2 %0, %1, %2, %0;" : "+l"(acc) : "l"(a), "l"(b))

// ---------------------------------------------------------------------------
// prep: one K-half (64) of the stacked GEMM [x;y] @ W1, transposed outputs.
//   kc half, rows 0..511 (x):  hxT_g[kc][h][r]  = x@W1[kc*64 : kc*64+64]
//                              (+ b1 folded into kc==0 half)
//   kc half, rows y:           nhyT_g[kc][h][r] = -(y@W1[128+kc*64 : ...])
// grid (16 r-tiles, 8 h-tiles, 2 kc) = 256 blocks, 256 threads.
// tile 64r x 64h x 64k, thread 4r x 4h, FMA2 inner with next-k prefetch.
// ---------------------------------------------------------------------------
__global__ void __launch_bounds__(256) prep_kernel(
    const float* __restrict__ x, const float* __restrict__ y,
    const float* __restrict__ W1, const float* __restrict__ b1)
{
    __shared__ float As[64][64];   // [k][r]
    __shared__ float Ws[64][64];   // [k][h]

    const bool isY = (blockIdx.x >= 8);
    const int r0   = (isY ? (blockIdx.x - 8) : blockIdx.x) * 64;
    const int h0   = blockIdx.y * 64;
    const int kc   = blockIdx.z;
    const float* __restrict__ in = isY ? y : x;
    const int wrow0 = (isY ? DX : 0) + kc * 64;

    const int tid = threadIdx.x;
    const int tr  = tid & 15;    // r frag = tr*4
    const int th  = tid >> 4;    // 0..15 : h frag = th*4

    uint64_t acc[4][2] = {};     // [h][r-pair], packed fp32x2

    // stage input tile transposed: As[k][r]
    const int sr = tid & 63;         // row
    const int sg = tid >> 6;         // k-group (0..3)
    #pragma unroll
    for (int m = 0; m < 4; m++) {
        int k0 = sg * 16 + m * 4;
        float4 v = *(const float4*)(in + (r0 + sr) * DX + kc * 64 + k0);
        As[k0 + 0][sr] = v.x;
        As[k0 + 1][sr] = v.y;
        As[k0 + 2][sr] = v.z;
        As[k0 + 3][sr] = v.w;
    }
    // stage W1 tile [64k x 64h]
    #pragma unroll
    for (int m = 0; m < 4; m++) {
        int f = tid + 256 * m;          // float4 index 0..1023
        int k = f >> 4, q = f & 15;
        *(float4*)&Ws[k][q * 4] =
            *(const float4*)(W1 + (wrow0 + k) * HH + h0 + q * 4);
    }
    __syncthreads();

    // fragment double-buffer over k
    float4 av = *(const float4*)&As[0][tr * 4];
    float4 wv = *(const float4*)&Ws[0][th * 4];
    #pragma unroll
    for (int k = 0; k < 64; k++) {
        float4 an, wn;
        if (k < 63) {
            an = *(const float4*)&As[k + 1][tr * 4];
            wn = *(const float4*)&Ws[k + 1][th * 4];
        }
        uint64_t a01, a23, wd;
        PACK2(a01, av.x, av.y);
        PACK2(a23, av.z, av.w);
        PACK2(wd, wv.x, wv.x);
        FMA2(acc[0][0], a01, wd);
        FMA2(acc[0][1], a23, wd);
        PACK2(wd, wv.y, wv.y);
        FMA2(acc[1][0], a01, wd);
        FMA2(acc[1][1], a23, wd);
        PACK2(wd, wv.z, wv.z);
        FMA2(acc[2][0], a01, wd);
        FMA2(acc[2][1], a23, wd);
        PACK2(wd, wv.w, wv.w);
        FMA2(acc[3][0], a01, wd);
        FMA2(acc[3][1], a23, wd);
        av = an; wv = wn;
    }

    float* outg = (isY ? nhyT_g : hxT_g) + kc * (HH * BN);
    #pragma unroll
    for (int c = 0; c < 4; c++) {
        const int h = h0 + th * 4 + c;
        float v0, v1, v2, v3;
        UNPACK2(v0, v1, acc[c][0]);
        UNPACK2(v2, v3, acc[c][1]);
        float4 o;
        if (isY) { o.x = -v0; o.y = -v1; o.z = -v2; o.w = -v3; }
        else {
            float bb = (kc == 0) ? b1[h] : 0.f;
            o.x = v0 + bb; o.y = v1 + bb; o.z = v2 + bb; o.w = v3 + bb;
        }
        *(float4*)(outg + h * BN + r0 + tr * 4) = o;
    }
}

// ---------------------------------------------------------------------------
// main: partial[z][i,j] = sum_{h in chunk z} max(hx[i,h], -hy[j,h])*w2[h]
//                         + sum_{h in chunk z} hy[j,h]*w2[h]        (gy part)
// grid (4 j-tiles, 8 i-tiles, 8 h-chunks) = 256 blocks, 256 threads.
// block tile 64i x 128j x 64h; thread tile 4i x 8j (j split {lo, hi+64}).
// staging adds the two K-halves produced by prep.
// ---------------------------------------------------------------------------
__global__ void __launch_bounds__(256) main_kernel(const float* __restrict__ W2)
{
    __shared__ float Axs[32][64];    // [h][i]
    __shared__ float Bys[32][128];   // [h][j] (negated hy)
    __shared__ float w2s[32];
    __shared__ float gybuf[2][128];

    const int j0 = blockIdx.x * 128;
    const int i0 = blockIdx.y * 64;
    const int hb = blockIdx.z * 64;

    const int tid = threadIdx.x;
    const int ti  = tid >> 4;    // 0..15 : i frag = ti*4
    const int tj  = tid & 15;    // j frags = tj*4 and 64 + tj*4
    const int gq  = tid >> 7;    // 0..1 gy strip
    const int gj  = tid & 127;   // gy j index

    float acc[4][8] = {};
    float gyp = 0.f;

    for (int s = 0; s < 2; s++) {
        const int h0 = hb + s * 32;
        __syncthreads();
        // stage hx chunk [32h x 64i] = half0 + half1
        #pragma unroll
        for (int m = 0; m < 2; m++) {
            int t = tid + 256 * m;          // 0..511
            int h = t >> 4, q = t & 15;
            const float* base = hxT_g + (h0 + h) * BN + i0 + q * 4;
            float4 u = *(const float4*)base;
            float4 v = *(const float4*)(base + HH * BN);
            u.x += v.x; u.y += v.y; u.z += v.z; u.w += v.w;
            *(float4*)&Axs[h][q * 4] = u;
        }
        // stage -hy chunk [32h x 128j] = half0 + half1
        #pragma unroll
        for (int m = 0; m < 4; m++) {
            int t = tid + 256 * m;          // 0..1023
            int h = t >> 5, q = t & 31;
            const float* base = nhyT_g + (h0 + h) * BN + j0 + q * 4;
            float4 u = *(const float4*)base;
            float4 v = *(const float4*)(base + HH * BN);
            u.x += v.x; u.y += v.y; u.z += v.z; u.w += v.w;
            *(float4*)&Bys[h][q * 4] = u;
        }
        if (tid < 32) w2s[tid] = W2[h0 + tid];
        __syncthreads();

        #pragma unroll 8
        for (int h = 0; h < 32; h++) {
            float4 a   = *(const float4*)&Axs[h][ti * 4];
            float4 b0  = *(const float4*)&Bys[h][tj * 4];
            float4 b1v = *(const float4*)&Bys[h][64 + tj * 4];
            const float w = w2s[h];
            float av[4] = {a.x, a.y, a.z, a.w};
            float bv[8] = {b0.x, b0.y, b0.z, b0.w, b1v.x, b1v.y, b1v.z, b1v.w};
            #pragma unroll
            for (int r = 0; r < 4; r++)
                #pragma unroll
                for (int c = 0; c < 8; c++)
                    acc[r][c] = fmaf(fmaxf(av[r], bv[c]), w, acc[r][c]);
        }

        // gy partial: strip gq covers h = gq*16 .. gq*16+15 of this stage
        #pragma unroll
        for (int hh = 0; hh < 16; hh++) {
            int h = gq * 16 + hh;
            gyp = fmaf(Bys[h][gj], w2s[h], gyp);   // accumulates -(hy*w2)
        }
    }

    __syncthreads();
    gybuf[gq][gj] = gyp;
    __syncthreads();

    float gyv[8];
    #pragma unroll
    for (int c = 0; c < 8; c++) {
        int jl = (c < 4) ? (tj * 4 + c) : (64 + tj * 4 + (c - 4));
        gyv[c] = -(gybuf[0][jl] + gybuf[1][jl]);
    }

    float* p = part_g + blockIdx.z * (BN * BN);
    #pragma unroll
    for (int r = 0; r < 4; r++) {
        float4 o0, o1;
        o0.x = acc[r][0] + gyv[0];
        o0.y = acc[r][1] + gyv[1];
        o0.z = acc[r][2] + gyv[2];
        o0.w = acc[r][3] + gyv[3];
        o1.x = acc[r][4] + gyv[4];
        o1.y = acc[r][5] + gyv[5];
        o1.z = acc[r][6] + gyv[6];
        o1.w = acc[r][7] + gyv[7];
        const int row = i0 + ti * 4 + r;
        *(float4*)(p + row * BN + j0 + tj * 4) = o0;
        *(float4*)(p + row * BN + j0 + 64 + tj * 4) = o1;
    }
}

// ---------------------------------------------------------------------------
// reduce: out = sum of 8 partials + b2
// ---------------------------------------------------------------------------
__global__ void __launch_bounds__(256) reduce_kernel(
    const float* __restrict__ b2, float* __restrict__ out)
{
    int idx = blockIdx.x * 256 + threadIdx.x;     // float4 index, 65536 total
    const float4* p = (const float4*)part_g;
    float4 s = p[idx];
    #pragma unroll
    for (int k = 1; k < 8; k++) {
        float4 v = p[idx + k * 65536];
        s.x += v.x; s.y += v.y; s.z += v.z; s.w += v.w;
    }
    float bb = b2[0];
    s.x += bb; s.y += bb; s.z += bb; s.w += bb;
    ((float4*)out)[idx] = s;
}

// ---------------------------------------------------------------------------
extern "C" void kernel_launch(void* const* d_in, const int* in_sizes, int n_in,
                              void* d_out, int out_size)
{
    const float* x  = (const float*)d_in[0];
    const float* y  = (const float*)d_in[1];
    const float* W1 = (const float*)d_in[2];
    const float* b1 = (const float*)d_in[3];
    const float* W2 = (const float*)d_in[4];
    const float* b2 = (const float*)d_in[5];
    float* out = (float*)d_out;

    prep_kernel<<<dim3(16, 8, 2), 256>>>(x, y, W1, b1);
    main_kernel<<<dim3(4, 8, 8), 256>>>(W2);
    reduce_kernel<<<256, 256>>>(b2, out);
}